// round 12
// baseline (speedup 1.0000x reference)
#include <cuda_runtime.h>

// SplineNetwork: 4 queries/warp, 8 lanes/query, 2 candidates/lane.
// B=16384 queries, 128x128 regular grid, K=9 NN + Keys cubic conv.
//   d_in[0] = x (16384,2) f32 | d_in[1] = weights (16384,1) f32
//   d_in[2] = control_points (16384,2) f32, cp[i*128+j] = (t_i, t_j)
// Output: (out (16384,1), x (16384,2)) -> 49152 floats.
//
// Interior (i0 in [1,125]^2): floor-4x4 window, 16 candidates as elements
// e = 2h+s (h = lane-in-group, s = slot), e == row-major == ascending global
// index. 9th-smallest via 16-elem bitonic (2 elems/lane: 4 in-reg + 6
// cross-lane stages). Stable selection == lax.top_k (strict < T9 plus
// lowest-global-index ties). Edge queries -> R8-certified 25-candidate
// full-warp path. D bit-matches reference:
//   D = rn(rn(x2s + rn(rn(cx^2)+rn(cy^2))) - 2*fma(x1,cy,rn(x0*cx)))

#define NGRID 128
#define KNN   9

__device__ __forceinline__ float process_q25(
    float2 xv, const float* __restrict__ cp, const float* __restrict__ wts,
    float inv_h, int lane)
{
    const unsigned FULL = 0xffffffffu;
    int nix = __float2int_rn((xv.x + 1.0f) * 63.5f);
    int niy = __float2int_rn((xv.y + 1.0f) * 63.5f);
    int sx = min(max(nix - 2, 0), NGRID - 5);
    int sy = min(max(niy - 2, 0), NGRID - 5);

    int row = (lane * 205) >> 10;
    int col = lane - row * 5;
    bool sentinel = lane >= 25;
    int ix = sx + (sentinel ? 0 : row);
    int iy = sy + (sentinel ? 0 : col);

    float cx = __ldg(&cp[ix << 8]);
    float cy = __ldg(&cp[2 * iy + 1]);
    float wv = __ldg(&wts[(ix << 7) + iy]);

    float x2s = __fadd_rn(__fmul_rn(xv.x, xv.x), __fmul_rn(xv.y, xv.y));
    float c2  = __fadd_rn(__fmul_rn(cx, cx), __fmul_rn(cy, cy));
    float dot = __fmaf_rn(xv.y, cy, __fmul_rn(xv.x, cx));
    float D   = __fsub_rn(__fadd_rn(x2s, c2), __fmul_rn(2.0f, dot));
    if (sentinel) D = __int_as_float(0x7f800000);

    float S = D;
#pragma unroll
    for (int k = 2; k <= 32; k <<= 1) {
#pragma unroll
        for (int j = k >> 1; j > 0; j >>= 1) {
            float Sp = __shfl_xor_sync(FULL, S, j);
            bool keepmin = ((lane & j) == 0) == ((lane & k) == 0);
            S = keepmin ? fminf(S, Sp) : fmaxf(S, Sp);
        }
    }
    float T9 = __shfl_sync(FULL, S, KNN - 1);

    unsigned below  = (1u << lane) - 1u;
    unsigned strict = __ballot_sync(FULL, D < T9);
    unsigned tie    = __ballot_sync(FULL, D == T9);
    bool sel = (D < T9) ||
               ((D == T9) && (__popc(tie & below) < KNN - __popc(strict)));

    float dxv = xv.x - cx, dyv = xv.y - cy;
    float a = sqrtf(fmaf(dxv, dxv, dyv * dyv)) * inv_h;
    float p1 = fmaf(fmaf(1.5f, a, -2.5f), a * a, 1.0f);
    float p2 = fmaf(fmaf(fmaf(-0.5f, a, 2.5f), a, -4.0f), a, 2.0f);
    float cv = (a < 1.0f) ? p1 : ((a < 2.0f) ? p2 : 0.0f);

    float val = sel ? (wv * cv) : 0.0f;
#pragma unroll
    for (int s = 16; s; s >>= 1)
        val += __shfl_xor_sync(FULL, val, s);
    return val;
}

// cross-lane bitonic stage on (a0,a1), lane-stride st
#define XSTAGE(st, lm, asc) {                          \
    float b0 = __shfl_xor_sync(FULL, a0, st);          \
    float b1 = __shfl_xor_sync(FULL, a1, st);          \
    bool keepmin = (lm) == (asc);                      \
    a0 = keepmin ? fminf(a0, b0) : fmaxf(a0, b0);      \
    a1 = keepmin ? fminf(a1, b1) : fmaxf(a1, b1); }

// in-register (slot-pair) stage: lower index = slot0
#define RSTAGE(asc) {                                  \
    bool ar = (asc);                                   \
    float mn = fminf(a0, a1), mx = fmaxf(a0, a1);      \
    a0 = ar ? mn : mx; a1 = ar ? mx : mn; }

__global__ __launch_bounds__(256) void spline_q4_kernel(
    const float* __restrict__ x,
    const float* __restrict__ wts,
    const float* __restrict__ cp,
    float* __restrict__ out,
    int batch)
{
    const unsigned FULL = 0xffffffffu;
    int lane = threadIdx.x & 31;
    int h = lane & 7;                       // lane within 8-lane group
    int w = blockIdx.x * (blockDim.x >> 5) + (threadIdx.x >> 5);
    int g = lane >> 3;                      // group 0..3
    int q = 4 * w + g;                      // this group's query

    float2 xq = __ldg((const float2*)x + q);

    // bandwidth h = ||x[0]-x[1]|| (smooth epilogue term)
    float4 h4 = __ldg((const float4*)x);
    float hdx = h4.x - h4.z, hdy = h4.y - h4.w;
    float inv_h = rsqrtf(fmaf(hdx, hdx, hdy * hdy));

    int i0x = (int)floorf((xq.x + 1.0f) * 63.5f);
    int i0y = (int)floorf((xq.y + 1.0f) * 63.5f);
    bool edge = (i0x < 1) | (i0x > 125) | (i0y < 1) | (i0y > 125);
    unsigned eb = __ballot_sync(FULL, edge);

    if (eb == 0u) {
        // ---- fast path: floor-4x4, elements e=2h+s, e == row*4+col
        int r  = h >> 1;
        int c0 = (h & 1) << 1;
        int ix  = i0x - 1 + r;
        int iy0 = i0y - 1 + c0;

        float cx  = __ldg(&cp[ix << 8]);
        float cy0 = __ldg(&cp[2 * iy0 + 1]);
        float cy1 = __ldg(&cp[2 * iy0 + 3]);
        float wv0 = __ldg(&wts[(ix << 7) + iy0]);
        float wv1 = __ldg(&wts[(ix << 7) + iy0 + 1]);

        // certified D chain (cxx/px hoisting value-identical)
        float x2s = __fadd_rn(__fmul_rn(xq.x, xq.x), __fmul_rn(xq.y, xq.y));
        float cxx = __fmul_rn(cx, cx);
        float px  = __fmul_rn(xq.x, cx);
        float D0 = __fsub_rn(__fadd_rn(x2s, __fadd_rn(cxx, __fmul_rn(cy0, cy0))),
                             __fmul_rn(2.0f, __fmaf_rn(xq.y, cy0, px)));
        float D1 = __fsub_rn(__fadd_rn(x2s, __fadd_rn(cxx, __fmul_rn(cy1, cy1))),
                             __fmul_rn(2.0f, __fmaf_rn(xq.y, cy1, px)));

        // ---- bitonic-16, 2 elems/lane, ascending in e
        float a0 = D0, a1 = D1;
        RSTAGE((h & 1) == 0);                        // k=2,  j=1
        XSTAGE(1, (h & 1) == 0, (h & 2) == 0);       // k=4,  j=2
        RSTAGE((h & 2) == 0);                        // k=4,  j=1
        XSTAGE(2, (h & 2) == 0, (h & 4) == 0);       // k=8,  j=4
        XSTAGE(1, (h & 1) == 0, (h & 4) == 0);       // k=8,  j=2
        RSTAGE((h & 4) == 0);                        // k=8,  j=1
        XSTAGE(4, (h & 4) == 0, true);               // k=16, j=8
        XSTAGE(2, (h & 2) == 0, true);               // k=16, j=4
        XSTAGE(1, (h & 1) == 0, true);               // k=16, j=2
        RSTAGE(true);                                // k=16, j=1
        // 9th smallest: e=8 -> h=4, slot0, within own group
        float T9 = __shfl_sync(FULL, a0, (lane & 24) | 4);

        // ---- stable selection (byte-sliced ballots serve all 4 groups)
        unsigned s0 = __ballot_sync(FULL, D0 < T9);
        unsigned s1 = __ballot_sync(FULL, D1 < T9);
        unsigned t0 = __ballot_sync(FULL, D0 == T9);
        unsigned t1 = __ballot_sync(FULL, D1 == T9);
        int gb = lane & 24;
        unsigned s0b = (s0 >> gb) & 0xFFu, s1b = (s1 >> gb) & 0xFFu;
        unsigned t0b = (t0 >> gb) & 0xFFu, t1b = (t1 >> gb) & 0xFFu;
        int m = __popc(s0b) + __popc(s1b);           // strictly better (<=8)
        unsigned belh = (1u << h) - 1u;
        int tp0 = __popc(t0b & belh) + __popc(t1b & belh);
        int tp1 = __popc(t0b & ((2u << h) - 1u)) + __popc(t1b & belh);
        bool sel0 = (D0 < T9) || ((D0 == T9) && (tp0 < KNN - m));
        bool sel1 = (D1 < T9) || ((D1 == T9) && (tp1 < KNN - m));

        // ---- Keys cubic conv epilogue
        float dxv = xq.x - cx;
        float dx2 = dxv * dxv;
        float dy0 = xq.y - cy0, dy1 = xq.y - cy1;
        float aa0 = sqrtf(fmaf(dy0, dy0, dx2)) * inv_h;
        float aa1 = sqrtf(fmaf(dy1, dy1, dx2)) * inv_h;
        float cva = (aa0 < 1.0f) ? fmaf(fmaf(1.5f, aa0, -2.5f), aa0 * aa0, 1.0f)
                  : (aa0 < 2.0f) ? fmaf(fmaf(fmaf(-0.5f, aa0, 2.5f), aa0, -4.0f), aa0, 2.0f)
                  : 0.0f;
        float cvb = (aa1 < 1.0f) ? fmaf(fmaf(1.5f, aa1, -2.5f), aa1 * aa1, 1.0f)
                  : (aa1 < 2.0f) ? fmaf(fmaf(fmaf(-0.5f, aa1, 2.5f), aa1, -4.0f), aa1, 2.0f)
                  : 0.0f;

        float val = (sel0 ? wv0 * cva : 0.0f) + (sel1 ? wv1 * cvb : 0.0f);
        // 3-step group sum (all 4 groups in parallel)
#pragma unroll
        for (int s = 4; s; s >>= 1)
            val += __shfl_xor_sync(FULL, val, s);

        if (h == 0) {
            out[q] = val;
            ((float2*)(out + batch))[q] = xq;
        }
    } else {
        // ---- edge fallback: R8-certified 25-candidate path, 4x serial
        int qb = 4 * w;
        float2 x0v = __ldg((const float2*)x + qb);
        float2 x1v = __ldg((const float2*)x + qb + 1);
        float2 x2v = __ldg((const float2*)x + qb + 2);
        float2 x3v = __ldg((const float2*)x + qb + 3);
        float v0 = process_q25(x0v, cp, wts, inv_h, lane);
        float v1 = process_q25(x1v, cp, wts, inv_h, lane);
        float v2 = process_q25(x2v, cp, wts, inv_h, lane);
        float v3 = process_q25(x3v, cp, wts, inv_h, lane);
        if (lane == 0) {
            out[qb] = v0; out[qb + 1] = v1; out[qb + 2] = v2; out[qb + 3] = v3;
            float2* xp = (float2*)(out + batch);
            xp[qb] = x0v; xp[qb + 1] = x1v; xp[qb + 2] = x2v; xp[qb + 3] = x3v;
        }
    }
}

extern "C" void kernel_launch(void* const* d_in, const int* in_sizes, int n_in,
                              void* d_out, int out_size)
{
    const float* x  = (const float*)d_in[0];
    const float* w  = (const float*)d_in[1];
    const float* cp = (const float*)d_in[2];
    float* out = (float*)d_out;
    int batch = in_sizes[0] / 2;              // 16384
    int block = 256;                          // 8 warps = 32 queries per CTA
    int qpb = (block / 32) * 4;
    int grid = (batch + qpb - 1) / qpb;       // 512, exact
    spline_q4_kernel<<<grid, block>>>(x, w, cp, out, batch);
    (void)n_in; (void)out_size;
}